// round 16
// baseline (speedup 1.0000x reference)
#include <cuda_runtime.h>
#include <cstdint>
#include <cstddef>

// Problem constants
#define BB 2
#define NN 1024
#define DD 1024
#define HH 4
#define KDIM 512
#define VDIM 1024
#define DK 128
#define DV 256
#define MROWS (BB*NN)
#define CHUNK 64
#define NCHUNK (NN/CHUNK)          // 16
#define TOTCHUNK (BB*HH*NCHUNK)    // 128

// Scratch layout (floats)
#define OFF_AG  0
#define OFF_V   2097152
#define OFF_GA  4194304
#define OFF_T16 6291456
#define OFF_O   6324224
#define OFF_Y   8421376
#define OFF_QH  10518528
#define OFF_KH  11567104
#define OFF_U   12615680
#define OFF_D   16809984
#define OFF_S   16826368
#define SCRATCH_TOTAL 21020672

__device__ float g_scratch[SCRATCH_TOTAL];

// ---------------------------------------------------------------------------
// TF32 helpers
// ---------------------------------------------------------------------------
__device__ __forceinline__ uint32_t f2tf32(float x) {
    uint32_t r;
    asm("cvt.rna.tf32.f32 %0, %1;" : "=r"(r) : "f"(x));
    return r;
}

__device__ __forceinline__ void mma_tf32(
    float* c, uint32_t a0, uint32_t a1, uint32_t a2, uint32_t a3,
    uint32_t b0, uint32_t b1)
{
    asm volatile(
        "mma.sync.aligned.m16n8k8.row.col.f32.tf32.tf32.f32 "
        "{%0,%1,%2,%3}, {%4,%5,%6,%7}, {%8,%9}, {%0,%1,%2,%3};"
        : "+f"(c[0]), "+f"(c[1]), "+f"(c[2]), "+f"(c[3])
        : "r"(a0), "r"(a1), "r"(a2), "r"(a3), "r"(b0), "r"(b1));
}

// ---------------------------------------------------------------------------
// TF32 tensor-core GEMM body (round-11 proven version). 128x128x16 tiles.
// ---------------------------------------------------------------------------
__device__ __forceinline__ void tf32_gemm_body(
    int N, int K,
    const float* __restrict__ A, const float* __restrict__ B, float* __restrict__ C,
    int bx, int by, const float* __restrict__ gA, float sgn)
{
    constexpr int BM = 128, BN = 128, BK = 16, LDA = 132;
    __shared__ uint32_t As[2][BK][LDA];
    __shared__ uint32_t Bs[2][BK][LDA];

    const int tid = threadIdx.x;
    const int lane = tid & 31, wid = tid >> 5;
    const int warpM = wid >> 2, warpN = wid & 3;
    const int lg = lane >> 2, lt = lane & 3;

    const float* Ab = A + (size_t)by * BM * K;
    const float* Bb = B + (size_t)bx * BN;

    const int ar = tid >> 2, ac = (tid & 3) * 4;
    const int br = tid >> 5, bc = (tid & 31) * 4;

    float acc[4][4][4];
#pragma unroll
    for (int mt = 0; mt < 4; mt++)
#pragma unroll
        for (int nt = 0; nt < 4; nt++)
#pragma unroll
            for (int i = 0; i < 4; i++) acc[mt][nt][i] = 0.f;

    float4 a40, a41, b40, b41;
    a40 = *reinterpret_cast<const float4*>(Ab + (size_t)ar * K + ac);
    a41 = *reinterpret_cast<const float4*>(Ab + (size_t)(ar + 64) * K + ac);
    b40 = *reinterpret_cast<const float4*>(Bb + (size_t)br * N + bc);
    b41 = *reinterpret_cast<const float4*>(Bb + (size_t)(br + 8) * N + bc);

    {
        As[0][ac + 0][ar] = f2tf32(a40.x); As[0][ac + 1][ar] = f2tf32(a40.y);
        As[0][ac + 2][ar] = f2tf32(a40.z); As[0][ac + 3][ar] = f2tf32(a40.w);
        As[0][ac + 0][ar + 64] = f2tf32(a41.x); As[0][ac + 1][ar + 64] = f2tf32(a41.y);
        As[0][ac + 2][ar + 64] = f2tf32(a41.z); As[0][ac + 3][ar + 64] = f2tf32(a41.w);
        uint4 u0 = make_uint4(f2tf32(b40.x), f2tf32(b40.y), f2tf32(b40.z), f2tf32(b40.w));
        uint4 u1 = make_uint4(f2tf32(b41.x), f2tf32(b41.y), f2tf32(b41.z), f2tf32(b41.w));
        *reinterpret_cast<uint4*>(&Bs[0][br][bc]) = u0;
        *reinterpret_cast<uint4*>(&Bs[0][br + 8][bc]) = u1;
    }
    __syncthreads();

    int buf = 0;
    for (int k0 = BK; k0 < K; k0 += BK) {
        a40 = *reinterpret_cast<const float4*>(Ab + (size_t)ar * K + k0 + ac);
        a41 = *reinterpret_cast<const float4*>(Ab + (size_t)(ar + 64) * K + k0 + ac);
        b40 = *reinterpret_cast<const float4*>(Bb + (size_t)(k0 + br) * N + bc);
        b41 = *reinterpret_cast<const float4*>(Bb + (size_t)(k0 + br + 8) * N + bc);

#pragma unroll
        for (int ks = 0; ks < 2; ks++) {
            const int kk = ks * 8;
            uint32_t bf[4][2];
#pragma unroll
            for (int nt = 0; nt < 4; nt++) {
                const int n0 = warpN * 32 + nt * 8 + lg;
                bf[nt][0] = Bs[buf][kk + lt][n0];
                bf[nt][1] = Bs[buf][kk + lt + 4][n0];
            }
#pragma unroll
            for (int mt = 0; mt < 4; mt++) {
                const int m0 = warpM * 64 + mt * 16 + lg;
                const uint32_t A0 = As[buf][kk + lt][m0];
                const uint32_t A1 = As[buf][kk + lt][m0 + 8];
                const uint32_t A2 = As[buf][kk + lt + 4][m0];
                const uint32_t A3 = As[buf][kk + lt + 4][m0 + 8];
#pragma unroll
                for (int nt = 0; nt < 4; nt++)
                    mma_tf32(acc[mt][nt], A0, A1, A2, A3, bf[nt][0], bf[nt][1]);
            }
        }

        const int nb = buf ^ 1;
        As[nb][ac + 0][ar] = f2tf32(a40.x); As[nb][ac + 1][ar] = f2tf32(a40.y);
        As[nb][ac + 2][ar] = f2tf32(a40.z); As[nb][ac + 3][ar] = f2tf32(a40.w);
        As[nb][ac + 0][ar + 64] = f2tf32(a41.x); As[nb][ac + 1][ar + 64] = f2tf32(a41.y);
        As[nb][ac + 2][ar + 64] = f2tf32(a41.z); As[nb][ac + 3][ar + 64] = f2tf32(a41.w);
        uint4 u0 = make_uint4(f2tf32(b40.x), f2tf32(b40.y), f2tf32(b40.z), f2tf32(b40.w));
        uint4 u1 = make_uint4(f2tf32(b41.x), f2tf32(b41.y), f2tf32(b41.z), f2tf32(b41.w));
        *reinterpret_cast<uint4*>(&Bs[nb][br][bc]) = u0;
        *reinterpret_cast<uint4*>(&Bs[nb][br + 8][bc]) = u1;
        __syncthreads();
        buf = nb;
    }

#pragma unroll
    for (int ks = 0; ks < 2; ks++) {
        const int kk = ks * 8;
        uint32_t bf[4][2];
#pragma unroll
        for (int nt = 0; nt < 4; nt++) {
            const int n0 = warpN * 32 + nt * 8 + lg;
            bf[nt][0] = Bs[buf][kk + lt][n0];
            bf[nt][1] = Bs[buf][kk + lt + 4][n0];
        }
#pragma unroll
        for (int mt = 0; mt < 4; mt++) {
            const int m0 = warpM * 64 + mt * 16 + lg;
            const uint32_t A0 = As[buf][kk + lt][m0];
            const uint32_t A1 = As[buf][kk + lt][m0 + 8];
            const uint32_t A2 = As[buf][kk + lt + 4][m0];
            const uint32_t A3 = As[buf][kk + lt + 4][m0 + 8];
#pragma unroll
            for (int nt = 0; nt < 4; nt++)
                mma_tf32(acc[mt][nt], A0, A1, A2, A3, bf[nt][0], bf[nt][1]);
        }
    }

    float* Cb = C + (size_t)by * BM * N + (size_t)bx * BN;
    if (gA) {
        const float* gb = gA + (size_t)by * BM * N + (size_t)bx * BN;
#pragma unroll
        for (int mt = 0; mt < 4; mt++) {
            const int r = warpM * 64 + mt * 16 + lg;
#pragma unroll
            for (int nt = 0; nt < 4; nt++) {
                const int c = warpN * 32 + nt * 8 + 2 * lt;
                float2 e0 = *reinterpret_cast<const float2*>(gb + (size_t)r * N + c);
                float2 e1 = *reinterpret_cast<const float2*>(gb + (size_t)(r + 8) * N + c);
                *reinterpret_cast<float2*>(Cb + (size_t)r * N + c) =
                    make_float2(acc[mt][nt][0] * __expf(sgn * e0.x),
                                acc[mt][nt][1] * __expf(sgn * e0.y));
                *reinterpret_cast<float2*>(Cb + (size_t)(r + 8) * N + c) =
                    make_float2(acc[mt][nt][2] * __expf(sgn * e1.x),
                                acc[mt][nt][3] * __expf(sgn * e1.y));
            }
        }
    } else {
#pragma unroll
        for (int mt = 0; mt < 4; mt++) {
            const int r = warpM * 64 + mt * 16 + lg;
#pragma unroll
            for (int nt = 0; nt < 4; nt++) {
                const int c = warpN * 32 + nt * 8 + 2 * lt;
                *reinterpret_cast<float2*>(Cb + (size_t)r * N + c) =
                    make_float2(acc[mt][nt][0], acc[mt][nt][1]);
                *reinterpret_cast<float2*>(Cb + (size_t)(r + 8) * N + c) =
                    make_float2(acc[mt][nt][2], acc[mt][nt][3]);
            }
        }
    }
}

// ---------------------------------------------------------------------------
// TF32 GEMM body, 128x64x16 tiles (for wave-filling out_gemm).
// 8 warps = 4M x 2N; warp tile 32x32 via 2x4 m16n8k8 fragments.
// Same BK=16 K-loop and per-element mma order as the 128x128 body.
// ---------------------------------------------------------------------------
__device__ __forceinline__ void tf32_gemm_body64(
    int N, int K,
    const float* __restrict__ A, const float* __restrict__ B, float* __restrict__ C,
    int bx, int by)
{
    constexpr int BM = 128, BN = 64, BK = 16, LDA = 132, LDB = 68;
    __shared__ uint32_t As[2][BK][LDA];
    __shared__ uint32_t Bs[2][BK][LDB];

    const int tid = threadIdx.x;
    const int lane = tid & 31, wid = tid >> 5;
    const int warpM = wid >> 1, warpN = wid & 1;
    const int lg = lane >> 2, lt = lane & 3;

    const float* Ab = A + (size_t)by * BM * K;
    const float* Bb = B + (size_t)bx * BN;

    const int ar = tid >> 2, ac = (tid & 3) * 4;   // A rows ar, ar+64
    const int br = tid >> 4, bc = (tid & 15) * 4;  // B: 16 rows x 64 cols, 1 float4/thr

    float acc[2][4][4];
#pragma unroll
    for (int mt = 0; mt < 2; mt++)
#pragma unroll
        for (int nt = 0; nt < 4; nt++)
#pragma unroll
            for (int i = 0; i < 4; i++) acc[mt][nt][i] = 0.f;

    float4 a40, a41, b40;
    a40 = *reinterpret_cast<const float4*>(Ab + (size_t)ar * K + ac);
    a41 = *reinterpret_cast<const float4*>(Ab + (size_t)(ar + 64) * K + ac);
    b40 = *reinterpret_cast<const float4*>(Bb + (size_t)br * N + bc);

    {
        As[0][ac + 0][ar] = f2tf32(a40.x); As[0][ac + 1][ar] = f2tf32(a40.y);
        As[0][ac + 2][ar] = f2tf32(a40.z); As[0][ac + 3][ar] = f2tf32(a40.w);
        As[0][ac + 0][ar + 64] = f2tf32(a41.x); As[0][ac + 1][ar + 64] = f2tf32(a41.y);
        As[0][ac + 2][ar + 64] = f2tf32(a41.z); As[0][ac + 3][ar + 64] = f2tf32(a41.w);
        uint4 u0 = make_uint4(f2tf32(b40.x), f2tf32(b40.y), f2tf32(b40.z), f2tf32(b40.w));
        *reinterpret_cast<uint4*>(&Bs[0][br][bc]) = u0;
    }
    __syncthreads();

    int buf = 0;
    for (int k0 = BK; k0 < K; k0 += BK) {
        a40 = *reinterpret_cast<const float4*>(Ab + (size_t)ar * K + k0 + ac);
        a41 = *reinterpret_cast<const float4*>(Ab + (size_t)(ar + 64) * K + k0 + ac);
        b40 = *reinterpret_cast<const float4*>(Bb + (size_t)(k0 + br) * N + bc);

#pragma unroll
        for (int ks = 0; ks < 2; ks++) {
            const int kk = ks * 8;
            uint32_t bf[4][2];
#pragma unroll
            for (int nt = 0; nt < 4; nt++) {
                const int n0 = warpN * 32 + nt * 8 + lg;
                bf[nt][0] = Bs[buf][kk + lt][n0];
                bf[nt][1] = Bs[buf][kk + lt + 4][n0];
            }
#pragma unroll
            for (int mt = 0; mt < 2; mt++) {
                const int m0 = warpM * 32 + mt * 16 + lg;
                const uint32_t A0 = As[buf][kk + lt][m0];
                const uint32_t A1 = As[buf][kk + lt][m0 + 8];
                const uint32_t A2 = As[buf][kk + lt + 4][m0];
                const uint32_t A3 = As[buf][kk + lt + 4][m0 + 8];
#pragma unroll
                for (int nt = 0; nt < 4; nt++)
                    mma_tf32(acc[mt][nt], A0, A1, A2, A3, bf[nt][0], bf[nt][1]);
            }
        }

        const int nb = buf ^ 1;
        As[nb][ac + 0][ar] = f2tf32(a40.x); As[nb][ac + 1][ar] = f2tf32(a40.y);
        As[nb][ac + 2][ar] = f2tf32(a40.z); As[nb][ac + 3][ar] = f2tf32(a40.w);
        As[nb][ac + 0][ar + 64] = f2tf32(a41.x); As[nb][ac + 1][ar + 64] = f2tf32(a41.y);
        As[nb][ac + 2][ar + 64] = f2tf32(a41.z); As[nb][ac + 3][ar + 64] = f2tf32(a41.w);
        uint4 u0 = make_uint4(f2tf32(b40.x), f2tf32(b40.y), f2tf32(b40.z), f2tf32(b40.w));
        *reinterpret_cast<uint4*>(&Bs[nb][br][bc]) = u0;
        __syncthreads();
        buf = nb;
    }

#pragma unroll
    for (int ks = 0; ks < 2; ks++) {
        const int kk = ks * 8;
        uint32_t bf[4][2];
#pragma unroll
        for (int nt = 0; nt < 4; nt++) {
            const int n0 = warpN * 32 + nt * 8 + lg;
            bf[nt][0] = Bs[buf][kk + lt][n0];
            bf[nt][1] = Bs[buf][kk + lt + 4][n0];
        }
#pragma unroll
        for (int mt = 0; mt < 2; mt++) {
            const int m0 = warpM * 32 + mt * 16 + lg;
            const uint32_t A0 = As[buf][kk + lt][m0];
            const uint32_t A1 = As[buf][kk + lt][m0 + 8];
            const uint32_t A2 = As[buf][kk + lt + 4][m0];
            const uint32_t A3 = As[buf][kk + lt + 4][m0 + 8];
#pragma unroll
            for (int nt = 0; nt < 4; nt++)
                mma_tf32(acc[mt][nt], A0, A1, A2, A3, bf[nt][0], bf[nt][1]);
        }
    }

    float* Cb = C + (size_t)by * BM * N + (size_t)bx * BN;
#pragma unroll
    for (int mt = 0; mt < 2; mt++) {
        const int r = warpM * 32 + mt * 16 + lg;
#pragma unroll
        for (int nt = 0; nt < 4; nt++) {
            const int c = warpN * 32 + nt * 8 + 2 * lt;
            *reinterpret_cast<float2*>(Cb + (size_t)r * N + c) =
                make_float2(acc[mt][nt][0], acc[mt][nt][1]);
            *reinterpret_cast<float2*>(Cb + (size_t)(r + 8) * N + c) =
                make_float2(acc[mt][nt][2], acc[mt][nt][3]);
        }
    }
}

// Fused projections: z=0 -> qh (gate e^{+A}), z=1 -> kh (gate e^{-A}),
// z=2 -> v, z=3 -> gaux.
__global__ __launch_bounds__(256) void proj_gemm_kernel(
    const float* __restrict__ x,
    const float* __restrict__ Bq, const float* __restrict__ Bk,
    const float* __restrict__ Bv, const float* __restrict__ Bg,
    float* __restrict__ Cq, float* __restrict__ Ck,
    float* __restrict__ Cv, float* __restrict__ Cg,
    const float* __restrict__ Ag)
{
    const int z = blockIdx.z;
    const int N = (z < 2) ? KDIM : VDIM;
    if ((int)blockIdx.x * 128 >= N) return;
    const float* B = (z == 0) ? Bq : (z == 1) ? Bk : (z == 2) ? Bv : Bg;
    float*       C = (z == 0) ? Cq : (z == 1) ? Ck : (z == 2) ? Cv : Cg;
    const float* gA = (z < 2) ? Ag : nullptr;
    const float sgn = (z == 0) ? 1.f : -1.f;
    tf32_gemm_body(N, DD, x, B, C, blockIdx.x, blockIdx.y, gA, sgn);
}

// Output projection with 128x64 tiles -> 256 CTAs (one full wave at 2 CTA/SM).
__global__ __launch_bounds__(256) void out_gemm_kernel(
    const float* __restrict__ A, const float* __restrict__ B, float* __restrict__ C)
{
    tf32_gemm_body64(DD, VDIM, A, B, C, blockIdx.x, blockIdx.y);
}

// ---------------------------------------------------------------------------
// Low-rank projection t16 = x @ Wgk1 (round-11 proven version)
// ---------------------------------------------------------------------------
__global__ __launch_bounds__(128) void proj_lr_kernel(
    const float* __restrict__ x, const float* __restrict__ Wgk1, float* __restrict__ t16)
{
    __shared__ float sx[1024];
    __shared__ float part[8][16];
    const int row = blockIdx.x;
    const int tid = threadIdx.x;
    for (int i = tid; i < 1024; i += 128) sx[i] = x[(size_t)row * 1024 + i];
    __syncthreads();
    const int col = tid & 15;
    const int seg = tid >> 4;
    float p = 0.f;
#pragma unroll 8
    for (int j = 0; j < 128; j++) {
        int kidx = seg * 128 + j;
        p = fmaf(sx[kidx], Wgk1[(size_t)kidx * 16 + col], p);
    }
    part[seg][col] = p;
    __syncthreads();
    if (tid < 16) {
        float s = 0.f;
#pragma unroll
        for (int s8 = 0; s8 < 8; s8++) s += part[s8][tid];
        t16[(size_t)row * 16 + tid] = s;
    }
}

// ---------------------------------------------------------------------------
// Gate cumsum (round-11 exact version)
// ---------------------------------------------------------------------------
__global__ __launch_bounds__(256) void gate_cum_kernel(
    const float* __restrict__ t16, const float* __restrict__ Wgk2,
    const float* __restrict__ bgk2,
    float* __restrict__ Ag, float* __restrict__ D)
{
    __shared__ float st[64][16];
    __shared__ float sg[64 * 128];

    const int c = blockIdx.x, bh = blockIdx.y;
    const int b = bh >> 2, h = bh & 3;
    const int tid = threadIdx.x;

    {
        const float* tp = t16 + (size_t)(b * NN + c * CHUNK) * 16;
        for (int i = tid; i < 1024; i += 256)
            (&st[0][0])[i] = tp[i];
    }
    __syncthreads();

    for (int i = tid; i < CHUNK * DK; i += 256) {
        const int t = i >> 7, d = i & 127;
        float z = bgk2[h * DK + d];
#pragma unroll
        for (int r = 0; r < 16; r++)
            z = fmaf(st[t][r], Wgk2[(size_t)r * KDIM + h * DK + d], z);
        float ls = fminf(z, 0.f) - __logf(1.f + __expf(-fabsf(z)));
        sg[i] = fmaxf(ls * 0.0625f, -3.f);
    }
    __syncthreads();

    {
        const int d = tid & 127, hl = tid >> 7;
        const int t0 = hl * 32;
#pragma unroll 4
        for (int t = t0 + 1; t < t0 + 32; t++)
            sg[t * 128 + d] += sg[(t - 1) * 128 + d];
    }
    __syncthreads();
    {
        const int d = tid & 127, hl = tid >> 7;
        if (hl == 1) {
            const float off = sg[31 * 128 + d];
#pragma unroll 4
            for (int t = 32; t < 64; t++)
                sg[t * 128 + d] += off;
        }
    }
    __syncthreads();

    const size_t gbase = ((size_t)(b * NN + c * CHUNK)) * KDIM + h * DK;
    for (int i = tid; i < CHUNK * DK; i += 256) {
        const int t = i >> 7, d = i & 127;
        Ag[gbase + (size_t)t * KDIM + d] = sg[i];
    }
    if (tid < 128)
        D[(bh * NCHUNK + c) * DK + tid] = __expf(sg[63 * 128 + tid]);
}

// ---------------------------------------------------------------------------
// Fused intra-chunk + U via single TF32 mma (round-11 version, unchanged).
// ---------------------------------------------------------------------------
__global__ __launch_bounds__(256) void intra_u_kernel(
    const float* __restrict__ qh, const float* __restrict__ kh,
    const float* __restrict__ v, const float* __restrict__ D,
    float* __restrict__ o, float* __restrict__ U)
{
    __shared__ uint32_t sQ[128 * 72];
    __shared__ uint32_t sK[128 * 72];
    __shared__ uint32_t sV[64 * 136];
    __shared__ float sD[128];

    const int vhalf = blockIdx.x & 1;
    const int cta = blockIdx.x >> 1;
    const int bh = cta >> 4, c = cta & 15;
    const int b = bh >> 2, h = bh & 3;
    const int tid = threadIdx.x;
    const int lane = tid & 31, w = tid >> 5;
    const int lg = lane >> 2, lt = lane & 3;
    const int wm = w >> 1, wn = w & 1;

    const size_t rbase = ((size_t)(b * NN + c * CHUNK)) * KDIM + h * DK;
    const size_t vbase = ((size_t)(b * NN + c * CHUNK)) * VDIM + h * DV;

    if (tid < 128) sD[tid] = D[(bh * NCHUNK + c) * DK + tid];

    for (int i = tid; i < 2048; i += 256) {
        const int s = i >> 5, c4 = (i & 31) * 4;
        float4 vv = *reinterpret_cast<const float4*>(
            v + vbase + (size_t)s * VDIM + vhalf * 128 + c4);
        sV[s * 136 + c4 + 0] = f2tf32(vv.x);
        sV[s * 136 + c4 + 1] = f2tf32(vv.y);
        sV[s * 136 + c4 + 2] = f2tf32(vv.z);
        sV[s * 136 + c4 + 3] = f2tf32(vv.w);
    }
    {
        const int t = tid >> 2;
        const int d0 = (tid & 3) * 4;
        const float* qp = qh + rbase + (size_t)t * KDIM;
        const float* kp = kh + rbase + (size_t)t * KDIM;
#pragma unroll
        for (int dd = 0; dd < 8; dd++) {
            const int d = d0 + dd * 16;
            float4 qv = *reinterpret_cast<const float4*>(qp + d);
            float4 kv = *reinterpret_cast<const float4*>(kp + d);
            sQ[(d + 0) * 72 + t] = f2tf32(qv.x); sQ[(d + 1) * 72 + t] = f2tf32(qv.y);
            sQ[(d + 2) * 72 + t] = f2tf32(qv.z); sQ[(d + 3) * 72 + t] = f2tf32(qv.w);
            sK[(d + 0) * 72 + t] = f2tf32(kv.x); sK[(d + 1) * 72 + t] = f2tf32(kv.y);
            sK[(d + 2) * 72 + t] = f2tf32(kv.z); sK[(d + 3) * 72 + t] = f2tf32(kv.w);
        }
    }
    __syncthreads();

    float acc1[4][4];
#pragma unroll
    for (int nt = 0; nt < 4; nt++)
#pragma unroll
        for (int i = 0; i < 4; i++) acc1[nt][i] = 0.f;

    {
        const int m0 = wm * 16 + lg;
#pragma unroll 4
        for (int k0 = 0; k0 < DK; k0 += 8) {
            const uint32_t A0 = sQ[(k0 + lt) * 72 + m0];
            const uint32_t A1 = sQ[(k0 + lt) * 72 + m0 + 8];
            const uint32_t A2 = sQ[(k0 + lt + 4) * 72 + m0];
            const uint32_t A3 = sQ[(k0 + lt + 4) * 72 + m0 + 8];
#pragma unroll
            for (int nt = 0; nt < 4; nt++) {
                const int n0 = wn * 32 + nt * 8 + lg;
                mma_tf32(acc1[nt], A0, A1, A2, A3,
                         sK[(k0 + lt) * 72 + n0], sK[(k0 + lt + 4) * 72 + n0]);
            }
        }
    }
    __syncthreads();

    uint32_t* sA  = sQ;
    uint32_t* sKU = sK;
    {
        const int r0 = wm * 16 + lg, r1 = r0 + 8;
#pragma unroll
        for (int nt = 0; nt < 4; nt++) {
            const int c0 = wn * 32 + nt * 8 + 2 * lt, c1 = c0 + 1;
            sA[c0 * 72 + r0] = f2tf32((c0 <= r0) ? acc1[nt][0] : 0.f);
            sA[c1 * 72 + r0] = f2tf32((c1 <= r0) ? acc1[nt][1] : 0.f);
            sA[c0 * 72 + r1] = f2tf32((c0 <= r1) ? acc1[nt][2] : 0.f);
            sA[c1 * 72 + r1] = f2tf32((c1 <= r1) ? acc1[nt][3] : 0.f);
        }
    }
    {
        const int s = tid >> 2;
        const int d0 = (tid & 3) * 4;
        const float* kp = kh + rbase + (size_t)s * KDIM;
#pragma unroll
        for (int dd = 0; dd < 8; dd++) {
            const int d = d0 + dd * 16;
            float4 kv = *reinterpret_cast<const float4*>(kp + d);
            sKU[s * 136 + d + 0] = f2tf32(kv.x * sD[d + 0]);
            sKU[s * 136 + d + 1] = f2tf32(kv.y * sD[d + 1]);
            sKU[s * 136 + d + 2] = f2tf32(kv.z * sD[d + 2]);
            sKU[s * 136 + d + 3] = f2tf32(kv.w * sD[d + 3]);
        }
    }
    __syncthreads();

    {
        float acc2[8][4];
#pragma unroll
        for (int nt = 0; nt < 8; nt++)
#pragma unroll
            for (int i = 0; i < 4; i++) acc2[nt][i] = 0.f;

        const int m0 = wm * 16 + lg;
#pragma unroll
        for (int k0 = 0; k0 < CHUNK; k0 += 8) {
            const uint32_t A0 = sA[(k0 + lt) * 72 + m0];
            const uint32_t A1 = sA[(k0 + lt) * 72 + m0 + 8];
            const uint32_t A2 = sA[(k0 + lt + 4) * 72 + m0];
            const uint32_t A3 = sA[(k0 + lt + 4) * 72 + m0 + 8];
#pragma unroll
            for (int nt = 0; nt < 8; nt++) {
                const int n0 = wn * 64 + nt * 8 + lg;
                mma_tf32(acc2[nt], A0, A1, A2, A3,
                         sV[(k0 + lt) * 136 + n0], sV[(k0 + lt + 4) * 136 + n0]);
            }
        }

        const int r0 = wm * 16 + lg, r1 = r0 + 8;
#pragma unroll
        for (int nt = 0; nt < 8; nt++) {
            const int c0 = wn * 64 + nt * 8 + 2 * lt;
            *reinterpret_cast<float2*>(o + vbase + (size_t)r0 * VDIM + vhalf * 128 + c0) =
                make_float2(acc2[nt][0], acc2[nt][1]);
            *reinterpret_cast<float2*>(o + vbase + (size_t)r1 * VDIM + vhalf * 128 + c0) =
                make_float2(acc2[nt][2], acc2[nt][3]);
        }
    }

    {
        float acc3[16][4];
#pragma unroll
        for (int nt = 0; nt < 16; nt++)
#pragma unroll
            for (int i = 0; i < 4; i++) acc3[nt][i] = 0.f;

        const int m0 = w * 16 + lg;
#pragma unroll
        for (int k0 = 0; k0 < CHUNK; k0 += 8) {
            const uint32_t A0 = sKU[(k0 + lt) * 136 + m0];
            const uint32_t A1 = sKU[(k0 + lt) * 136 + m0 + 8];
            const uint32_t A2 = sKU[(k0 + lt + 4) * 136 + m0];
            const uint32_t A3 = sKU[(k0 + lt + 4) * 136 + m0 + 8];
#pragma unroll
            for (int nt = 0; nt < 16; nt++) {
                const int n0 = nt * 8 + lg;
                mma_tf32(acc3[nt], A0, A1, A2, A3,
                         sV[(k0 + lt) * 136 + n0], sV[(k0 + lt + 4) * 136 + n0]);
            }
        }

        float* Ub = U + ((size_t)(bh * NCHUNK + c) * DK) * DV + vhalf * 128;
        const int d0 = w * 16 + lg, d1 = d0 + 8;
#pragma unroll
        for (int nt = 0; nt < 16; nt++) {
            const int c0 = nt * 8 + 2 * lt;
            *reinterpret_cast<float2*>(Ub + (size_t)d0 * DV + c0) =
                make_float2(acc3[nt][0], acc3[nt][1]);
            *reinterpret_cast<float2*>(Ub + (size_t)d1 * DV + c0) =
                make_float2(acc3[nt][2], acc3[nt][3]);
        }
    }
}

// ---------------------------------------------------------------------------
// Elementwise chunk-state scan
// ---------------------------------------------------------------------------
__global__ __launch_bounds__(256) void state_scan_kernel(
    const float* __restrict__ U, const float* __restrict__ D, float* __restrict__ S)
{
    const int bh = blockIdx.y;
    const int e = blockIdx.x * 256 + threadIdx.x;
    const int d = e >> 6;
    const int vq = (e & 63) * 4;

    float4 s = make_float4(0.f, 0.f, 0.f, 0.f);
#pragma unroll
    for (int c = 0; c < NCHUNK; c++) {
        const size_t base = ((size_t)((bh * NCHUNK + c) * DK) + d) * DV + vq;
        if (c > 0)
            *reinterpret_cast<float4*>(S + base) = s;
        const float dc = D[(bh * NCHUNK + c) * DK + d];
        const float4 u = *reinterpret_cast<const float4*>(U + base);
        s.x = fmaf(s.x, dc, u.x);
        s.y = fmaf(s.y, dc, u.y);
        s.z = fmaf(s.z, dc, u.z);
        s.w = fmaf(s.w, dc, u.w);
    }
}

// ---------------------------------------------------------------------------
// Inter-chunk output via single TF32 mma, double-buffered k-slabs
// (round-15 version, unchanged).
// ---------------------------------------------------------------------------
__global__ __launch_bounds__(256) void inter2_kernel(
    const float* __restrict__ qh, const float* __restrict__ S, float* __restrict__ o)
{
    __shared__ uint32_t Qs[2][16 * 72];
    __shared__ uint32_t Ss[2][16 * 136];

    const int vhalf = blockIdx.x;
    const int j = blockIdx.y;
    const int bh = j / 15;
    const int c = j % 15 + 1;
    const int b = bh >> 2, h = bh & 3;
    const int tid = threadIdx.x;
    const int lane = tid & 31, w = tid >> 5;
    const int lg = lane >> 2, lt = lane & 3;
    const int wm = w >> 1, wn = w & 1;

    const size_t qbase = ((size_t)(b * NN + c * CHUNK)) * KDIM + h * DK;
    const size_t Sbase = ((size_t)((bh * NCHUNK + c) * DK)) * DV + vhalf * 128;
    const size_t obase = ((size_t)(b * NN + c * CHUNK)) * VDIM + h * DV + vhalf * 128;

    const int qt = tid >> 2;
    const int qk = (tid & 3) * 4;
    const int sr = tid >> 5;
    const int sc = (tid & 31) * 4;

    float acc[8][4];
#pragma unroll
    for (int nt = 0; nt < 8; nt++)
#pragma unroll
        for (int i = 0; i < 4; i++) acc[nt][i] = 0.f;

    {
        float4 qv = *reinterpret_cast<const float4*>(
            qh + qbase + (size_t)qt * KDIM + qk);
        Qs[0][(qk + 0) * 72 + qt] = f2tf32(qv.x);
        Qs[0][(qk + 1) * 72 + qt] = f2tf32(qv.y);
        Qs[0][(qk + 2) * 72 + qt] = f2tf32(qv.z);
        Qs[0][(qk + 3) * 72 + qt] = f2tf32(qv.w);
        float4 s0 = *reinterpret_cast<const float4*>(
            S + Sbase + (size_t)sr * DV + sc);
        float4 s1 = *reinterpret_cast<const float4*>(
            S + Sbase + (size_t)(sr + 8) * DV + sc);
        Ss[0][sr * 136 + sc + 0] = f2tf32(s0.x);
        Ss[0][sr * 136 + sc + 1] = f2tf32(s0.y);
        Ss[0][sr * 136 + sc + 2] = f2tf32(s0.z);
        Ss[0][sr * 136 + sc + 3] = f2tf32(s0.w);
        Ss[0][(sr + 8) * 136 + sc + 0] = f2tf32(s1.x);
        Ss[0][(sr + 8) * 136 + sc + 1] = f2tf32(s1.y);
        Ss[0][(sr + 8) * 136 + sc + 2] = f2tf32(s1.z);
        Ss[0][(sr + 8) * 136 + sc + 3] = f2tf32(s1.w);
    }
    __syncthreads();

    int buf = 0;
    for (int k0 = 0; k0 < DK; k0 += 16) {
        if (k0 + 16 < DK) {
            const int nb = buf ^ 1;
            float4 qv = *reinterpret_cast<const float4*>(
                qh + qbase + (size_t)qt * KDIM + k0 + 16 + qk);
            Qs[nb][(qk + 0) * 72 + qt] = f2tf32(qv.x);
            Qs[nb][(qk + 1) * 72 + qt] = f2tf32(qv.y);
            Qs[nb][(qk + 2) * 72 + qt] = f2tf32(qv.z);
            Qs[nb][(qk + 3) * 72 + qt] = f2tf32(qv.w);
            float4 s0 = *reinterpret_cast<const float4*>(
                S + Sbase + (size_t)(k0 + 16 + sr) * DV + sc);
            float4 s1 = *reinterpret_cast<const float4*>(
                S + Sbase + (size_t)(k0 + 16 + sr + 8) * DV + sc);
            Ss[nb][sr * 136 + sc + 0] = f2tf32(s0.x);
            Ss[nb][sr * 136 + sc + 1] = f2tf32(s0.y);
            Ss[nb][sr * 136 + sc + 2] = f2tf32(s0.z);
            Ss[nb][sr * 136 + sc + 3] = f2tf32(s0.w);
            Ss[nb][(sr + 8) * 136 + sc + 0] = f2tf32(s1.x);
            Ss[nb][(sr + 8) * 136 + sc + 1] = f2tf32(s1.y);
            Ss[nb][(sr + 8) * 136 + sc + 2] = f2tf32(s1.z);
            Ss[nb][(sr + 8) * 136 + sc + 3] = f2tf32(s1.w);
        }

        const int m0 = wm * 16 + lg;
#pragma unroll
        for (int ks = 0; ks < 16; ks += 8) {
            const uint32_t A0 = Qs[buf][(ks + lt) * 72 + m0];
            const uint32_t A1 = Qs[buf][(ks + lt) * 72 + m0 + 8];
            const uint32_t A2 = Qs[buf][(ks + lt + 4) * 72 + m0];
            const uint32_t A3 = Qs[buf][(ks + lt + 4) * 72 + m0 + 8];
#pragma unroll
            for (int nt = 0; nt < 8; nt++) {
                const int n0 = wn * 64 + nt * 8 + lg;
                mma_tf32(acc[nt], A0, A1, A2, A3,
                         Ss[buf][(ks + lt) * 136 + n0],
                         Ss[buf][(ks + lt + 4) * 136 + n0]);
            }
        }
        __syncthreads();
        buf ^= 1;
    }

    const int r0 = wm * 16 + lg, r1 = r0 + 8;
#pragma unroll
    for (int nt = 0; nt < 8; nt++) {
        const int c0 = wn * 64 + nt * 8 + 2 * lt;
        float* op0 = o + obase + (size_t)r0 * VDIM + c0;
        float* op1 = o + obase + (size_t)r1 * VDIM + c0;
        float2 v0 = *reinterpret_cast<const float2*>(op0);
        float2 v1 = *reinterpret_cast<const float2*>(op1);
        v0.x += acc[nt][0]; v0.y += acc[nt][1];
        v1.x += acc[nt][2]; v1.y += acc[nt][3];
        *reinterpret_cast<float2*>(op0) = v0;
        *reinterpret_cast<float2*>(op1) = v1;
    }
}

// ---------------------------------------------------------------------------
// RMSNorm + SiLU gating
// ---------------------------------------------------------------------------
__global__ __launch_bounds__(256) void norm_gate_kernel(
    const float* __restrict__ o, const float* __restrict__ gaux,
    const float* __restrict__ rms_w, float* __restrict__ y)
{
    const int row = blockIdx.x;
    const int tid = threadIdx.x;
    const size_t base = (size_t)row * VDIM + tid * 4;

    const float4 ov = *reinterpret_cast<const float4*>(o + base);
    float ss = ov.x * ov.x + ov.y * ov.y + ov.z * ov.z + ov.w * ov.w;
#pragma unroll
    for (int off = 16; off; off >>= 1)
        ss += __shfl_xor_sync(0xffffffffu, ss, off);

    __shared__ float ws[8];
    const int warp = tid >> 5, lane = tid & 31;
    if (lane == 0) ws[warp] = ss;
    __syncthreads();

    const int hw = (tid >> 6) << 1;
    const float tot = ws[hw] + ws[hw + 1];
    const float scale = rsqrtf(tot * (1.f / 256.f) + 1e-5f);

    const float4 gv = *reinterpret_cast<const float4*>(gaux + base);
    const int dv = (tid * 4) & 255;
    const float w0 = rms_w[dv + 0], w1 = rms_w[dv + 1], w2 = rms_w[dv + 2], w3 = rms_w[dv + 3];

    float4 r;
    r.x = ov.x * scale * w0 * (gv.x / (1.f + __expf(-gv.x)));
    r.y = ov.y * scale * w1 * (gv.y / (1.f + __expf(-gv.y)));
    r.z = ov.z * scale * w2 * (gv.z / (1.f + __expf(-gv.z)));
    r.w = ov.w * scale * w3 * (gv.w / (1.f + __expf(-gv.w)));
    *reinterpret_cast<float4*>(y + base) = r;
}

// ---------------------------------------------------------------------------
extern "C" void kernel_launch(void* const* d_in, const int* in_sizes, int n_in,
                              void* d_out, int out_size)
{
    const float* x    = (const float*)d_in[0];
    const float* Wq   = (const float*)d_in[1];
    const float* Wk   = (const float*)d_in[2];
    const float* Wv   = (const float*)d_in[3];
    const float* Wg   = (const float*)d_in[4];
    const float* Wgk1 = (const float*)d_in[5];
    const float* Wgk2 = (const float*)d_in[6];
    const float* bgk2 = (const float*)d_in[7];
    const float* Wout = (const float*)d_in[8];
    const float* rmsw = (const float*)d_in[9];
    float* out = (float*)d_out;

    float* scratch = nullptr;
    cudaGetSymbolAddress((void**)&scratch, g_scratch);
    float* Ag   = scratch + OFF_AG;
    float* v    = scratch + OFF_V;
    float* ga   = scratch + OFF_GA;
    float* t16  = scratch + OFF_T16;
    float* o    = scratch + OFF_O;
    float* y    = scratch + OFF_Y;
    float* qhb  = scratch + OFF_QH;
    float* khb  = scratch + OFF_KH;
    float* Ub   = scratch + OFF_U;
    float* Db   = scratch + OFF_D;
    float* Sb   = scratch + OFF_S;

    // gate path (x only)
    proj_lr_kernel<<<MROWS, 128>>>(x, Wgk1, t16);
    gate_cum_kernel<<<dim3(NCHUNK, BB * HH), 256>>>(t16, Wgk2, bgk2, Ag, Db);

    // fused projections with gate scaling in epilogue (q->qh, k->kh)
    proj_gemm_kernel<<<dim3(VDIM / 128, MROWS / 128, 4), 256>>>(
        x, Wq, Wk, Wv, Wg, qhb, khb, v, ga, Ag);

    // chunked GLA: tensor-core intra+U, scan, tensor-core inter
    intra_u_kernel<<<TOTCHUNK * 2, 256>>>(qhb, khb, v, Db, o, Ub);
    state_scan_kernel<<<dim3(32, BB * HH), 256>>>(Ub, Db, Sb);
    inter2_kernel<<<dim3(2, BB * HH * (NCHUNK - 1)), 256>>>(qhb, Sb, o);

    // epilogue
    norm_gate_kernel<<<MROWS, 256>>>(o, ga, rmsw, y);
    out_gemm_kernel<<<dim3(VDIM / 64, MROWS / 128), 256>>>(y, Wout, out);
}

// round 17
// speedup vs baseline: 1.0713x; 1.0713x over previous
#include <cuda_runtime.h>
#include <cstdint>
#include <cstddef>

// Problem constants
#define BB 2
#define NN 1024
#define DD 1024
#define HH 4
#define KDIM 512
#define VDIM 1024
#define DK 128
#define DV 256
#define MROWS (BB*NN)
#define CHUNK 64
#define NCHUNK (NN/CHUNK)          // 16
#define TOTCHUNK (BB*HH*NCHUNK)    // 128

// Scratch layout (floats)
#define OFF_AG  0
#define OFF_V   2097152
#define OFF_GA  4194304
#define OFF_T16 6291456
#define OFF_O   6324224
#define OFF_Y   8421376
#define OFF_QH  10518528
#define OFF_KH  11567104
#define OFF_U   12615680
#define OFF_D   16809984
#define OFF_S   16826368
#define SCRATCH_TOTAL 21020672

__device__ float g_scratch[SCRATCH_TOTAL];

// ---------------------------------------------------------------------------
// TF32 helpers
// ---------------------------------------------------------------------------
__device__ __forceinline__ uint32_t f2tf32(float x) {
    uint32_t r;
    asm("cvt.rna.tf32.f32 %0, %1;" : "=r"(r) : "f"(x));
    return r;
}

__device__ __forceinline__ void mma_tf32(
    float* c, uint32_t a0, uint32_t a1, uint32_t a2, uint32_t a3,
    uint32_t b0, uint32_t b1)
{
    asm volatile(
        "mma.sync.aligned.m16n8k8.row.col.f32.tf32.tf32.f32 "
        "{%0,%1,%2,%3}, {%4,%5,%6,%7}, {%8,%9}, {%0,%1,%2,%3};"
        : "+f"(c[0]), "+f"(c[1]), "+f"(c[2]), "+f"(c[3])
        : "r"(a0), "r"(a1), "r"(a2), "r"(a3), "r"(b0), "r"(b1));
}

// ---------------------------------------------------------------------------
// TF32 tensor-core GEMM body (round-11 proven version). 128x128x16 tiles.
// ---------------------------------------------------------------------------
__device__ __forceinline__ void tf32_gemm_body(
    int N, int K,
    const float* __restrict__ A, const float* __restrict__ B, float* __restrict__ C,
    int bx, int by, const float* __restrict__ gA, float sgn)
{
    constexpr int BM = 128, BN = 128, BK = 16, LDA = 132;
    __shared__ uint32_t As[2][BK][LDA];
    __shared__ uint32_t Bs[2][BK][LDA];

    const int tid = threadIdx.x;
    const int lane = tid & 31, wid = tid >> 5;
    const int warpM = wid >> 2, warpN = wid & 3;
    const int lg = lane >> 2, lt = lane & 3;

    const float* Ab = A + (size_t)by * BM * K;
    const float* Bb = B + (size_t)bx * BN;

    const int ar = tid >> 2, ac = (tid & 3) * 4;
    const int br = tid >> 5, bc = (tid & 31) * 4;

    float acc[4][4][4];
#pragma unroll
    for (int mt = 0; mt < 4; mt++)
#pragma unroll
        for (int nt = 0; nt < 4; nt++)
#pragma unroll
            for (int i = 0; i < 4; i++) acc[mt][nt][i] = 0.f;

    float4 a40, a41, b40, b41;
    a40 = *reinterpret_cast<const float4*>(Ab + (size_t)ar * K + ac);
    a41 = *reinterpret_cast<const float4*>(Ab + (size_t)(ar + 64) * K + ac);
    b40 = *reinterpret_cast<const float4*>(Bb + (size_t)br * N + bc);
    b41 = *reinterpret_cast<const float4*>(Bb + (size_t)(br + 8) * N + bc);

    {
        As[0][ac + 0][ar] = f2tf32(a40.x); As[0][ac + 1][ar] = f2tf32(a40.y);
        As[0][ac + 2][ar] = f2tf32(a40.z); As[0][ac + 3][ar] = f2tf32(a40.w);
        As[0][ac + 0][ar + 64] = f2tf32(a41.x); As[0][ac + 1][ar + 64] = f2tf32(a41.y);
        As[0][ac + 2][ar + 64] = f2tf32(a41.z); As[0][ac + 3][ar + 64] = f2tf32(a41.w);
        uint4 u0 = make_uint4(f2tf32(b40.x), f2tf32(b40.y), f2tf32(b40.z), f2tf32(b40.w));
        uint4 u1 = make_uint4(f2tf32(b41.x), f2tf32(b41.y), f2tf32(b41.z), f2tf32(b41.w));
        *reinterpret_cast<uint4*>(&Bs[0][br][bc]) = u0;
        *reinterpret_cast<uint4*>(&Bs[0][br + 8][bc]) = u1;
    }
    __syncthreads();

    int buf = 0;
    for (int k0 = BK; k0 < K; k0 += BK) {
        a40 = *reinterpret_cast<const float4*>(Ab + (size_t)ar * K + k0 + ac);
        a41 = *reinterpret_cast<const float4*>(Ab + (size_t)(ar + 64) * K + k0 + ac);
        b40 = *reinterpret_cast<const float4*>(Bb + (size_t)(k0 + br) * N + bc);
        b41 = *reinterpret_cast<const float4*>(Bb + (size_t)(k0 + br + 8) * N + bc);

#pragma unroll
        for (int ks = 0; ks < 2; ks++) {
            const int kk = ks * 8;
            uint32_t bf[4][2];
#pragma unroll
            for (int nt = 0; nt < 4; nt++) {
                const int n0 = warpN * 32 + nt * 8 + lg;
                bf[nt][0] = Bs[buf][kk + lt][n0];
                bf[nt][1] = Bs[buf][kk + lt + 4][n0];
            }
#pragma unroll
            for (int mt = 0; mt < 4; mt++) {
                const int m0 = warpM * 64 + mt * 16 + lg;
                const uint32_t A0 = As[buf][kk + lt][m0];
                const uint32_t A1 = As[buf][kk + lt][m0 + 8];
                const uint32_t A2 = As[buf][kk + lt + 4][m0];
                const uint32_t A3 = As[buf][kk + lt + 4][m0 + 8];
#pragma unroll
                for (int nt = 0; nt < 4; nt++)
                    mma_tf32(acc[mt][nt], A0, A1, A2, A3, bf[nt][0], bf[nt][1]);
            }
        }

        const int nb = buf ^ 1;
        As[nb][ac + 0][ar] = f2tf32(a40.x); As[nb][ac + 1][ar] = f2tf32(a40.y);
        As[nb][ac + 2][ar] = f2tf32(a40.z); As[nb][ac + 3][ar] = f2tf32(a40.w);
        As[nb][ac + 0][ar + 64] = f2tf32(a41.x); As[nb][ac + 1][ar + 64] = f2tf32(a41.y);
        As[nb][ac + 2][ar + 64] = f2tf32(a41.z); As[nb][ac + 3][ar + 64] = f2tf32(a41.w);
        uint4 u0 = make_uint4(f2tf32(b40.x), f2tf32(b40.y), f2tf32(b40.z), f2tf32(b40.w));
        uint4 u1 = make_uint4(f2tf32(b41.x), f2tf32(b41.y), f2tf32(b41.z), f2tf32(b41.w));
        *reinterpret_cast<uint4*>(&Bs[nb][br][bc]) = u0;
        *reinterpret_cast<uint4*>(&Bs[nb][br + 8][bc]) = u1;
        __syncthreads();
        buf = nb;
    }

#pragma unroll
    for (int ks = 0; ks < 2; ks++) {
        const int kk = ks * 8;
        uint32_t bf[4][2];
#pragma unroll
        for (int nt = 0; nt < 4; nt++) {
            const int n0 = warpN * 32 + nt * 8 + lg;
            bf[nt][0] = Bs[buf][kk + lt][n0];
            bf[nt][1] = Bs[buf][kk + lt + 4][n0];
        }
#pragma unroll
        for (int mt = 0; mt < 4; mt++) {
            const int m0 = warpM * 64 + mt * 16 + lg;
            const uint32_t A0 = As[buf][kk + lt][m0];
            const uint32_t A1 = As[buf][kk + lt][m0 + 8];
            const uint32_t A2 = As[buf][kk + lt + 4][m0];
            const uint32_t A3 = As[buf][kk + lt + 4][m0 + 8];
#pragma unroll
            for (int nt = 0; nt < 4; nt++)
                mma_tf32(acc[mt][nt], A0, A1, A2, A3, bf[nt][0], bf[nt][1]);
        }
    }

    float* Cb = C + (size_t)by * BM * N + (size_t)bx * BN;
    if (gA) {
        const float* gb = gA + (size_t)by * BM * N + (size_t)bx * BN;
#pragma unroll
        for (int mt = 0; mt < 4; mt++) {
            const int r = warpM * 64 + mt * 16 + lg;
#pragma unroll
            for (int nt = 0; nt < 4; nt++) {
                const int c = warpN * 32 + nt * 8 + 2 * lt;
                float2 e0 = *reinterpret_cast<const float2*>(gb + (size_t)r * N + c);
                float2 e1 = *reinterpret_cast<const float2*>(gb + (size_t)(r + 8) * N + c);
                *reinterpret_cast<float2*>(Cb + (size_t)r * N + c) =
                    make_float2(acc[mt][nt][0] * __expf(sgn * e0.x),
                                acc[mt][nt][1] * __expf(sgn * e0.y));
                *reinterpret_cast<float2*>(Cb + (size_t)(r + 8) * N + c) =
                    make_float2(acc[mt][nt][2] * __expf(sgn * e1.x),
                                acc[mt][nt][3] * __expf(sgn * e1.y));
            }
        }
    } else {
#pragma unroll
        for (int mt = 0; mt < 4; mt++) {
            const int r = warpM * 64 + mt * 16 + lg;
#pragma unroll
            for (int nt = 0; nt < 4; nt++) {
                const int c = warpN * 32 + nt * 8 + 2 * lt;
                *reinterpret_cast<float2*>(Cb + (size_t)r * N + c) =
                    make_float2(acc[mt][nt][0], acc[mt][nt][1]);
                *reinterpret_cast<float2*>(Cb + (size_t)(r + 8) * N + c) =
                    make_float2(acc[mt][nt][2], acc[mt][nt][3]);
            }
        }
    }
}

// Fused projections: z=0 -> qh (gate e^{+A}), z=1 -> kh (gate e^{-A}),
// z=2 -> v, z=3 -> gaux.
__global__ __launch_bounds__(256) void proj_gemm_kernel(
    const float* __restrict__ x,
    const float* __restrict__ Bq, const float* __restrict__ Bk,
    const float* __restrict__ Bv, const float* __restrict__ Bg,
    float* __restrict__ Cq, float* __restrict__ Ck,
    float* __restrict__ Cv, float* __restrict__ Cg,
    const float* __restrict__ Ag)
{
    const int z = blockIdx.z;
    const int N = (z < 2) ? KDIM : VDIM;
    if ((int)blockIdx.x * 128 >= N) return;
    const float* B = (z == 0) ? Bq : (z == 1) ? Bk : (z == 2) ? Bv : Bg;
    float*       C = (z == 0) ? Cq : (z == 1) ? Ck : (z == 2) ? Cv : Cg;
    const float* gA = (z < 2) ? Ag : nullptr;
    const float sgn = (z == 0) ? 1.f : -1.f;
    tf32_gemm_body(N, DD, x, B, C, blockIdx.x, blockIdx.y, gA, sgn);
}

__global__ __launch_bounds__(256) void out_gemm_kernel(
    const float* __restrict__ A, const float* __restrict__ B, float* __restrict__ C)
{
    tf32_gemm_body(DD, VDIM, A, B, C, blockIdx.x, blockIdx.y, nullptr, 0.f);
}

// ---------------------------------------------------------------------------
// Low-rank projection t16 = x @ Wgk1 (round-11 proven version)
// ---------------------------------------------------------------------------
__global__ __launch_bounds__(128) void proj_lr_kernel(
    const float* __restrict__ x, const float* __restrict__ Wgk1, float* __restrict__ t16)
{
    __shared__ float sx[1024];
    __shared__ float part[8][16];
    const int row = blockIdx.x;
    const int tid = threadIdx.x;
    for (int i = tid; i < 1024; i += 128) sx[i] = x[(size_t)row * 1024 + i];
    __syncthreads();
    const int col = tid & 15;
    const int seg = tid >> 4;
    float p = 0.f;
#pragma unroll 8
    for (int j = 0; j < 128; j++) {
        int kidx = seg * 128 + j;
        p = fmaf(sx[kidx], Wgk1[(size_t)kidx * 16 + col], p);
    }
    part[seg][col] = p;
    __syncthreads();
    if (tid < 16) {
        float s = 0.f;
#pragma unroll
        for (int s8 = 0; s8 < 8; s8++) s += part[s8][tid];
        t16[(size_t)row * 16 + tid] = s;
    }
}

// ---------------------------------------------------------------------------
// Gate cumsum (round-11 exact version)
// ---------------------------------------------------------------------------
__global__ __launch_bounds__(256) void gate_cum_kernel(
    const float* __restrict__ t16, const float* __restrict__ Wgk2,
    const float* __restrict__ bgk2,
    float* __restrict__ Ag, float* __restrict__ D)
{
    __shared__ float st[64][16];
    __shared__ float sg[64 * 128];

    const int c = blockIdx.x, bh = blockIdx.y;
    const int b = bh >> 2, h = bh & 3;
    const int tid = threadIdx.x;

    {
        const float* tp = t16 + (size_t)(b * NN + c * CHUNK) * 16;
        for (int i = tid; i < 1024; i += 256)
            (&st[0][0])[i] = tp[i];
    }
    __syncthreads();

    for (int i = tid; i < CHUNK * DK; i += 256) {
        const int t = i >> 7, d = i & 127;
        float z = bgk2[h * DK + d];
#pragma unroll
        for (int r = 0; r < 16; r++)
            z = fmaf(st[t][r], Wgk2[(size_t)r * KDIM + h * DK + d], z);
        float ls = fminf(z, 0.f) - __logf(1.f + __expf(-fabsf(z)));
        sg[i] = fmaxf(ls * 0.0625f, -3.f);
    }
    __syncthreads();

    {
        const int d = tid & 127, hl = tid >> 7;
        const int t0 = hl * 32;
#pragma unroll 4
        for (int t = t0 + 1; t < t0 + 32; t++)
            sg[t * 128 + d] += sg[(t - 1) * 128 + d];
    }
    __syncthreads();
    {
        const int d = tid & 127, hl = tid >> 7;
        if (hl == 1) {
            const float off = sg[31 * 128 + d];
#pragma unroll 4
            for (int t = 32; t < 64; t++)
                sg[t * 128 + d] += off;
        }
    }
    __syncthreads();

    const size_t gbase = ((size_t)(b * NN + c * CHUNK)) * KDIM + h * DK;
    for (int i = tid; i < CHUNK * DK; i += 256) {
        const int t = i >> 7, d = i & 127;
        Ag[gbase + (size_t)t * KDIM + d] = sg[i];
    }
    if (tid < 128)
        D[(bh * NCHUNK + c) * DK + tid] = __expf(sg[63 * 128 + tid]);
}

// ---------------------------------------------------------------------------
// Fused intra-chunk + U via single TF32 mma (round-11 version, unchanged).
// ---------------------------------------------------------------------------
__global__ __launch_bounds__(256) void intra_u_kernel(
    const float* __restrict__ qh, const float* __restrict__ kh,
    const float* __restrict__ v, const float* __restrict__ D,
    float* __restrict__ o, float* __restrict__ U)
{
    __shared__ uint32_t sQ[128 * 72];
    __shared__ uint32_t sK[128 * 72];
    __shared__ uint32_t sV[64 * 136];
    __shared__ float sD[128];

    const int vhalf = blockIdx.x & 1;
    const int cta = blockIdx.x >> 1;
    const int bh = cta >> 4, c = cta & 15;
    const int b = bh >> 2, h = bh & 3;
    const int tid = threadIdx.x;
    const int lane = tid & 31, w = tid >> 5;
    const int lg = lane >> 2, lt = lane & 3;
    const int wm = w >> 1, wn = w & 1;

    const size_t rbase = ((size_t)(b * NN + c * CHUNK)) * KDIM + h * DK;
    const size_t vbase = ((size_t)(b * NN + c * CHUNK)) * VDIM + h * DV;

    if (tid < 128) sD[tid] = D[(bh * NCHUNK + c) * DK + tid];

    for (int i = tid; i < 2048; i += 256) {
        const int s = i >> 5, c4 = (i & 31) * 4;
        float4 vv = *reinterpret_cast<const float4*>(
            v + vbase + (size_t)s * VDIM + vhalf * 128 + c4);
        sV[s * 136 + c4 + 0] = f2tf32(vv.x);
        sV[s * 136 + c4 + 1] = f2tf32(vv.y);
        sV[s * 136 + c4 + 2] = f2tf32(vv.z);
        sV[s * 136 + c4 + 3] = f2tf32(vv.w);
    }
    {
        const int t = tid >> 2;
        const int d0 = (tid & 3) * 4;
        const float* qp = qh + rbase + (size_t)t * KDIM;
        const float* kp = kh + rbase + (size_t)t * KDIM;
#pragma unroll
        for (int dd = 0; dd < 8; dd++) {
            const int d = d0 + dd * 16;
            float4 qv = *reinterpret_cast<const float4*>(qp + d);
            float4 kv = *reinterpret_cast<const float4*>(kp + d);
            sQ[(d + 0) * 72 + t] = f2tf32(qv.x); sQ[(d + 1) * 72 + t] = f2tf32(qv.y);
            sQ[(d + 2) * 72 + t] = f2tf32(qv.z); sQ[(d + 3) * 72 + t] = f2tf32(qv.w);
            sK[(d + 0) * 72 + t] = f2tf32(kv.x); sK[(d + 1) * 72 + t] = f2tf32(kv.y);
            sK[(d + 2) * 72 + t] = f2tf32(kv.z); sK[(d + 3) * 72 + t] = f2tf32(kv.w);
        }
    }
    __syncthreads();

    float acc1[4][4];
#pragma unroll
    for (int nt = 0; nt < 4; nt++)
#pragma unroll
        for (int i = 0; i < 4; i++) acc1[nt][i] = 0.f;

    {
        const int m0 = wm * 16 + lg;
#pragma unroll 4
        for (int k0 = 0; k0 < DK; k0 += 8) {
            const uint32_t A0 = sQ[(k0 + lt) * 72 + m0];
            const uint32_t A1 = sQ[(k0 + lt) * 72 + m0 + 8];
            const uint32_t A2 = sQ[(k0 + lt + 4) * 72 + m0];
            const uint32_t A3 = sQ[(k0 + lt + 4) * 72 + m0 + 8];
#pragma unroll
            for (int nt = 0; nt < 4; nt++) {
                const int n0 = wn * 32 + nt * 8 + lg;
                mma_tf32(acc1[nt], A0, A1, A2, A3,
                         sK[(k0 + lt) * 72 + n0], sK[(k0 + lt + 4) * 72 + n0]);
            }
        }
    }
    __syncthreads();

    uint32_t* sA  = sQ;
    uint32_t* sKU = sK;
    {
        const int r0 = wm * 16 + lg, r1 = r0 + 8;
#pragma unroll
        for (int nt = 0; nt < 4; nt++) {
            const int c0 = wn * 32 + nt * 8 + 2 * lt, c1 = c0 + 1;
            sA[c0 * 72 + r0] = f2tf32((c0 <= r0) ? acc1[nt][0] : 0.f);
            sA[c1 * 72 + r0] = f2tf32((c1 <= r0) ? acc1[nt][1] : 0.f);
            sA[c0 * 72 + r1] = f2tf32((c0 <= r1) ? acc1[nt][2] : 0.f);
            sA[c1 * 72 + r1] = f2tf32((c1 <= r1) ? acc1[nt][3] : 0.f);
        }
    }
    {
        const int s = tid >> 2;
        const int d0 = (tid & 3) * 4;
        const float* kp = kh + rbase + (size_t)s * KDIM;
#pragma unroll
        for (int dd = 0; dd < 8; dd++) {
            const int d = d0 + dd * 16;
            float4 kv = *reinterpret_cast<const float4*>(kp + d);
            sKU[s * 136 + d + 0] = f2tf32(kv.x * sD[d + 0]);
            sKU[s * 136 + d + 1] = f2tf32(kv.y * sD[d + 1]);
            sKU[s * 136 + d + 2] = f2tf32(kv.z * sD[d + 2]);
            sKU[s * 136 + d + 3] = f2tf32(kv.w * sD[d + 3]);
        }
    }
    __syncthreads();

    {
        float acc2[8][4];
#pragma unroll
        for (int nt = 0; nt < 8; nt++)
#pragma unroll
            for (int i = 0; i < 4; i++) acc2[nt][i] = 0.f;

        const int m0 = wm * 16 + lg;
#pragma unroll
        for (int k0 = 0; k0 < CHUNK; k0 += 8) {
            const uint32_t A0 = sA[(k0 + lt) * 72 + m0];
            const uint32_t A1 = sA[(k0 + lt) * 72 + m0 + 8];
            const uint32_t A2 = sA[(k0 + lt + 4) * 72 + m0];
            const uint32_t A3 = sA[(k0 + lt + 4) * 72 + m0 + 8];
#pragma unroll
            for (int nt = 0; nt < 8; nt++) {
                const int n0 = wn * 64 + nt * 8 + lg;
                mma_tf32(acc2[nt], A0, A1, A2, A3,
                         sV[(k0 + lt) * 136 + n0], sV[(k0 + lt + 4) * 136 + n0]);
            }
        }

        const int r0 = wm * 16 + lg, r1 = r0 + 8;
#pragma unroll
        for (int nt = 0; nt < 8; nt++) {
            const int c0 = wn * 64 + nt * 8 + 2 * lt;
            *reinterpret_cast<float2*>(o + vbase + (size_t)r0 * VDIM + vhalf * 128 + c0) =
                make_float2(acc2[nt][0], acc2[nt][1]);
            *reinterpret_cast<float2*>(o + vbase + (size_t)r1 * VDIM + vhalf * 128 + c0) =
                make_float2(acc2[nt][2], acc2[nt][3]);
        }
    }

    {
        float acc3[16][4];
#pragma unroll
        for (int nt = 0; nt < 16; nt++)
#pragma unroll
            for (int i = 0; i < 4; i++) acc3[nt][i] = 0.f;

        const int m0 = w * 16 + lg;
#pragma unroll
        for (int k0 = 0; k0 < CHUNK; k0 += 8) {
            const uint32_t A0 = sKU[(k0 + lt) * 136 + m0];
            const uint32_t A1 = sKU[(k0 + lt) * 136 + m0 + 8];
            const uint32_t A2 = sKU[(k0 + lt + 4) * 136 + m0];
            const uint32_t A3 = sKU[(k0 + lt + 4) * 136 + m0 + 8];
#pragma unroll
            for (int nt = 0; nt < 16; nt++) {
                const int n0 = nt * 8 + lg;
                mma_tf32(acc3[nt], A0, A1, A2, A3,
                         sV[(k0 + lt) * 136 + n0], sV[(k0 + lt + 4) * 136 + n0]);
            }
        }

        float* Ub = U + ((size_t)(bh * NCHUNK + c) * DK) * DV + vhalf * 128;
        const int d0 = w * 16 + lg, d1 = d0 + 8;
#pragma unroll
        for (int nt = 0; nt < 16; nt++) {
            const int c0 = nt * 8 + 2 * lt;
            *reinterpret_cast<float2*>(Ub + (size_t)d0 * DV + c0) =
                make_float2(acc3[nt][0], acc3[nt][1]);
            *reinterpret_cast<float2*>(Ub + (size_t)d1 * DV + c0) =
                make_float2(acc3[nt][2], acc3[nt][3]);
        }
    }
}

// ---------------------------------------------------------------------------
// Elementwise chunk-state scan
// ---------------------------------------------------------------------------
__global__ __launch_bounds__(256) void state_scan_kernel(
    const float* __restrict__ U, const float* __restrict__ D, float* __restrict__ S)
{
    const int bh = blockIdx.y;
    const int e = blockIdx.x * 256 + threadIdx.x;
    const int d = e >> 6;
    const int vq = (e & 63) * 4;

    float4 s = make_float4(0.f, 0.f, 0.f, 0.f);
#pragma unroll
    for (int c = 0; c < NCHUNK; c++) {
        const size_t base = ((size_t)((bh * NCHUNK + c) * DK) + d) * DV + vq;
        if (c > 0)
            *reinterpret_cast<float4*>(S + base) = s;
        const float dc = D[(bh * NCHUNK + c) * DK + d];
        const float4 u = *reinterpret_cast<const float4*>(U + base);
        s.x = fmaf(s.x, dc, u.x);
        s.y = fmaf(s.y, dc, u.y);
        s.z = fmaf(s.z, dc, u.z);
        s.w = fmaf(s.w, dc, u.w);
    }
}

// ---------------------------------------------------------------------------
// Inter-chunk output via single TF32 mma, double-buffered k-slabs
// (round-15 version, unchanged).
// ---------------------------------------------------------------------------
__global__ __launch_bounds__(256) void inter2_kernel(
    const float* __restrict__ qh, const float* __restrict__ S, float* __restrict__ o)
{
    __shared__ uint32_t Qs[2][16 * 72];
    __shared__ uint32_t Ss[2][16 * 136];

    const int vhalf = blockIdx.x;
    const int j = blockIdx.y;
    const int bh = j / 15;
    const int c = j % 15 + 1;
    const int b = bh >> 2, h = bh & 3;
    const int tid = threadIdx.x;
    const int lane = tid & 31, w = tid >> 5;
    const int lg = lane >> 2, lt = lane & 3;
    const int wm = w >> 1, wn = w & 1;

    const size_t qbase = ((size_t)(b * NN + c * CHUNK)) * KDIM + h * DK;
    const size_t Sbase = ((size_t)((bh * NCHUNK + c) * DK)) * DV + vhalf * 128;
    const size_t obase = ((size_t)(b * NN + c * CHUNK)) * VDIM + h * DV + vhalf * 128;

    const int qt = tid >> 2;
    const int qk = (tid & 3) * 4;
    const int sr = tid >> 5;
    const int sc = (tid & 31) * 4;

    float acc[8][4];
#pragma unroll
    for (int nt = 0; nt < 8; nt++)
#pragma unroll
        for (int i = 0; i < 4; i++) acc[nt][i] = 0.f;

    {
        float4 qv = *reinterpret_cast<const float4*>(
            qh + qbase + (size_t)qt * KDIM + qk);
        Qs[0][(qk + 0) * 72 + qt] = f2tf32(qv.x);
        Qs[0][(qk + 1) * 72 + qt] = f2tf32(qv.y);
        Qs[0][(qk + 2) * 72 + qt] = f2tf32(qv.z);
        Qs[0][(qk + 3) * 72 + qt] = f2tf32(qv.w);
        float4 s0 = *reinterpret_cast<const float4*>(
            S + Sbase + (size_t)sr * DV + sc);
        float4 s1 = *reinterpret_cast<const float4*>(
            S + Sbase + (size_t)(sr + 8) * DV + sc);
        Ss[0][sr * 136 + sc + 0] = f2tf32(s0.x);
        Ss[0][sr * 136 + sc + 1] = f2tf32(s0.y);
        Ss[0][sr * 136 + sc + 2] = f2tf32(s0.z);
        Ss[0][sr * 136 + sc + 3] = f2tf32(s0.w);
        Ss[0][(sr + 8) * 136 + sc + 0] = f2tf32(s1.x);
        Ss[0][(sr + 8) * 136 + sc + 1] = f2tf32(s1.y);
        Ss[0][(sr + 8) * 136 + sc + 2] = f2tf32(s1.z);
        Ss[0][(sr + 8) * 136 + sc + 3] = f2tf32(s1.w);
    }
    __syncthreads();

    int buf = 0;
    for (int k0 = 0; k0 < DK; k0 += 16) {
        if (k0 + 16 < DK) {
            const int nb = buf ^ 1;
            float4 qv = *reinterpret_cast<const float4*>(
                qh + qbase + (size_t)qt * KDIM + k0 + 16 + qk);
            Qs[nb][(qk + 0) * 72 + qt] = f2tf32(qv.x);
            Qs[nb][(qk + 1) * 72 + qt] = f2tf32(qv.y);
            Qs[nb][(qk + 2) * 72 + qt] = f2tf32(qv.z);
            Qs[nb][(qk + 3) * 72 + qt] = f2tf32(qv.w);
            float4 s0 = *reinterpret_cast<const float4*>(
                S + Sbase + (size_t)(k0 + 16 + sr) * DV + sc);
            float4 s1 = *reinterpret_cast<const float4*>(
                S + Sbase + (size_t)(k0 + 16 + sr + 8) * DV + sc);
            Ss[nb][sr * 136 + sc + 0] = f2tf32(s0.x);
            Ss[nb][sr * 136 + sc + 1] = f2tf32(s0.y);
            Ss[nb][sr * 136 + sc + 2] = f2tf32(s0.z);
            Ss[nb][sr * 136 + sc + 3] = f2tf32(s0.w);
            Ss[nb][(sr + 8) * 136 + sc + 0] = f2tf32(s1.x);
            Ss[nb][(sr + 8) * 136 + sc + 1] = f2tf32(s1.y);
            Ss[nb][(sr + 8) * 136 + sc + 2] = f2tf32(s1.z);
            Ss[nb][(sr + 8) * 136 + sc + 3] = f2tf32(s1.w);
        }

        const int m0 = wm * 16 + lg;
#pragma unroll
        for (int ks = 0; ks < 16; ks += 8) {
            const uint32_t A0 = Qs[buf][(ks + lt) * 72 + m0];
            const uint32_t A1 = Qs[buf][(ks + lt) * 72 + m0 + 8];
            const uint32_t A2 = Qs[buf][(ks + lt + 4) * 72 + m0];
            const uint32_t A3 = Qs[buf][(ks + lt + 4) * 72 + m0 + 8];
#pragma unroll
            for (int nt = 0; nt < 8; nt++) {
                const int n0 = wn * 64 + nt * 8 + lg;
                mma_tf32(acc[nt], A0, A1, A2, A3,
                         Ss[buf][(ks + lt) * 136 + n0],
                         Ss[buf][(ks + lt + 4) * 136 + n0]);
            }
        }
        __syncthreads();
        buf ^= 1;
    }

    const int r0 = wm * 16 + lg, r1 = r0 + 8;
#pragma unroll
    for (int nt = 0; nt < 8; nt++) {
        const int c0 = wn * 64 + nt * 8 + 2 * lt;
        float* op0 = o + obase + (size_t)r0 * VDIM + c0;
        float* op1 = o + obase + (size_t)r1 * VDIM + c0;
        float2 v0 = *reinterpret_cast<const float2*>(op0);
        float2 v1 = *reinterpret_cast<const float2*>(op1);
        v0.x += acc[nt][0]; v0.y += acc[nt][1];
        v1.x += acc[nt][2]; v1.y += acc[nt][3];
        *reinterpret_cast<float2*>(op0) = v0;
        *reinterpret_cast<float2*>(op1) = v1;
    }
}

// ---------------------------------------------------------------------------
// RMSNorm + SiLU gating
// ---------------------------------------------------------------------------
__global__ __launch_bounds__(256) void norm_gate_kernel(
    const float* __restrict__ o, const float* __restrict__ gaux,
    const float* __restrict__ rms_w, float* __restrict__ y)
{
    const int row = blockIdx.x;
    const int tid = threadIdx.x;
    const size_t base = (size_t)row * VDIM + tid * 4;

    const float4 ov = *reinterpret_cast<const float4*>(o + base);
    float ss = ov.x * ov.x + ov.y * ov.y + ov.z * ov.z + ov.w * ov.w;
#pragma unroll
    for (int off = 16; off; off >>= 1)
        ss += __shfl_xor_sync(0xffffffffu, ss, off);

    __shared__ float ws[8];
    const int warp = tid >> 5, lane = tid & 31;
    if (lane == 0) ws[warp] = ss;
    __syncthreads();

    const int hw = (tid >> 6) << 1;
    const float tot = ws[hw] + ws[hw + 1];
    const float scale = rsqrtf(tot * (1.f / 256.f) + 1e-5f);

    const float4 gv = *reinterpret_cast<const float4*>(gaux + base);
    const int dv = (tid * 4) & 255;
    const float w0 = rms_w[dv + 0], w1 = rms_w[dv + 1], w2 = rms_w[dv + 2], w3 = rms_w[dv + 3];

    float4 r;
    r.x = ov.x * scale * w0 * (gv.x / (1.f + __expf(-gv.x)));
    r.y = ov.y * scale * w1 * (gv.y / (1.f + __expf(-gv.y)));
    r.z = ov.z * scale * w2 * (gv.z / (1.f + __expf(-gv.z)));
    r.w = ov.w * scale * w3 * (gv.w / (1.f + __expf(-gv.w)));
    *reinterpret_cast<float4*>(y + base) = r;
}

// ---------------------------------------------------------------------------
extern "C" void kernel_launch(void* const* d_in, const int* in_sizes, int n_in,
                              void* d_out, int out_size)
{
    const float* x    = (const float*)d_in[0];
    const float* Wq   = (const float*)d_in[1];
    const float* Wk   = (const float*)d_in[2];
    const float* Wv   = (const float*)d_in[3];
    const float* Wg   = (const float*)d_in[4];
    const float* Wgk1 = (const float*)d_in[5];
    const float* Wgk2 = (const float*)d_in[6];
    const float* bgk2 = (const float*)d_in[7];
    const float* Wout = (const float*)d_in[8];
    const float* rmsw = (const float*)d_in[9];
    float* out = (float*)d_out;

    float* scratch = nullptr;
    cudaGetSymbolAddress((void**)&scratch, g_scratch);
    float* Ag   = scratch + OFF_AG;
    float* v    = scratch + OFF_V;
    float* ga   = scratch + OFF_GA;
    float* t16  = scratch + OFF_T16;
    float* o    = scratch + OFF_O;
    float* y    = scratch + OFF_Y;
    float* qhb  = scratch + OFF_QH;
    float* khb  = scratch + OFF_KH;
    float* Ub   = scratch + OFF_U;
    float* Db   = scratch + OFF_D;
    float* Sb   = scratch + OFF_S;

    // gate path (x only)
    proj_lr_kernel<<<MROWS, 128>>>(x, Wgk1, t16);
    gate_cum_kernel<<<dim3(NCHUNK, BB * HH), 256>>>(t16, Wgk2, bgk2, Ag, Db);

    // fused projections with gate scaling in epilogue (q->qh, k->kh)
    proj_gemm_kernel<<<dim3(VDIM / 128, MROWS / 128, 4), 256>>>(
        x, Wq, Wk, Wv, Wg, qhb, khb, v, ga, Ag);

    // chunked GLA: tensor-core intra+U, scan, tensor-core inter
    intra_u_kernel<<<TOTCHUNK * 2, 256>>>(qhb, khb, v, Db, o, Ub);
    state_scan_kernel<<<dim3(32, BB * HH), 256>>>(Ub, Db, Sb);
    inter2_kernel<<<dim3(2, BB * HH * (NCHUNK - 1)), 256>>>(qhb, Sb, o);

    // epilogue
    norm_gate_kernel<<<MROWS, 256>>>(o, ga, rmsw, y);
    out_gemm_kernel<<<dim3(VDIM / 128, MROWS / 128), 256>>>(y, Wout, out);
}